// round 2
// baseline (speedup 1.0000x reference)
#include <cuda_runtime.h>

#define B_ 256
#define C_ 2048
#define N_ 288
#define K_ 6

// scratch (no allocations allowed)
__device__ unsigned char g_assign[B_ * N_];
__device__ float g_inv[B_ * K_];

// ---------------------------------------------------------------------------
// Kernel A: per-batch cluster assignment.
// Grid = B (256), block = 288 threads (thread <-> spatial position n).
// Streams x[b, c, :] rows (fully coalesced), clusters staged in shared in two
// 24KB halves. dist_k = x_norm + c_norm[k] - 2*dot_k, argmin with first-min
// tie break (matches jnp.argmin).
// ---------------------------------------------------------------------------
__global__ void __launch_bounds__(N_) assign_kernel(const float* __restrict__ x,
                                                    const float* __restrict__ cl) {
    __shared__ float sCl[K_][1024];   // 24 KB: half of the clusters
    __shared__ float sCn[K_];
    __shared__ int   sCnt[K_];

    const int b = blockIdx.x;
    const int t = threadIdx.x;        // 0..287  (n index)
    const int w = t >> 5;
    const int l = t & 31;

    if (t < K_) sCnt[t] = 0;

    // c_norm[k] = sum_c cl[k][c]^2  (warp k reduces row k, read from global)
    if (w < K_) {
        float s = 0.f;
        for (int c = l; c < C_; c += 32) {
            float v = __ldg(&cl[w * C_ + c]);
            s = fmaf(v, v, s);
        }
        #pragma unroll
        for (int o = 16; o; o >>= 1) s += __shfl_xor_sync(0xffffffffu, s, o);
        if (l == 0) sCn[w] = s;
    }

    const float* xb = x + (size_t)b * ((size_t)C_ * N_) + t;

    float d[K_];
    #pragma unroll
    for (int k = 0; k < K_; k++) d[k] = 0.f;
    float xn = 0.f;

    for (int half = 0; half < 2; ++half) {
        __syncthreads();
        // stage 6 x 1024 cluster values into shared (coalesced)
        for (int i = t; i < K_ * 1024; i += N_) {
            int k = i >> 10;
            int cc = i & 1023;
            sCl[k][cc] = cl[k * C_ + half * 1024 + cc];
        }
        __syncthreads();

        const float* xh = xb + (size_t)half * 1024 * N_;
        #pragma unroll 1
        for (int c = 0; c < 1024; c += 8) {
            float v[8];
            #pragma unroll
            for (int u = 0; u < 8; u++) v[u] = xh[(size_t)(c + u) * N_];
            #pragma unroll
            for (int u = 0; u < 8; u++) xn = fmaf(v[u], v[u], xn);
            #pragma unroll
            for (int k = 0; k < K_; k++) {
                float4 q0 = *(const float4*)&sCl[k][c];
                float4 q1 = *(const float4*)&sCl[k][c + 4];
                float a = d[k];
                a = fmaf(v[0], q0.x, a);
                a = fmaf(v[1], q0.y, a);
                a = fmaf(v[2], q0.z, a);
                a = fmaf(v[3], q0.w, a);
                a = fmaf(v[4], q1.x, a);
                a = fmaf(v[5], q1.y, a);
                a = fmaf(v[6], q1.z, a);
                a = fmaf(v[7], q1.w, a);
                d[k] = a;
            }
        }
    }

    // argmin_k (xn + c_norm[k] - 2*dot_k), first index wins ties
    int   a  = 0;
    float bd = (xn + sCn[0]) - 2.0f * d[0];
    #pragma unroll
    for (int k = 1; k < K_; k++) {
        float e = (xn + sCn[k]) - 2.0f * d[k];
        if (e < bd) { bd = e; a = k; }
    }
    g_assign[b * N_ + t] = (unsigned char)a;

    atomicAdd(&sCnt[a], 1);
    __syncthreads();
    if (t < K_) {
        int cnt = sCnt[t];
        g_inv[b * K_ + t] = (cnt > 0) ? (1.0f / (float)cnt) : 0.0f;
    }
}

// ---------------------------------------------------------------------------
// Kernel B: scatter-mean.
// Grid = 1024 CTAs (4 per batch), 256 threads (8 warps). Warp handles one
// (b, c) row per iteration (64 rows total), same b throughout -> one-hot
// float masks m[9][6] precomputed once per warp; per element = 1 FFMA per k.
// ---------------------------------------------------------------------------
__global__ void __launch_bounds__(256) sum_kernel(const float* __restrict__ x,
                                                  float* __restrict__ out) {
    const int b = blockIdx.x >> 2;
    const int q = blockIdx.x & 3;
    const int w = threadIdx.x >> 5;
    const int l = threadIdx.x & 31;

    // per-lane one-hot masks for its 9 spatial positions (fixed for this b)
    float m[9][K_];
    #pragma unroll
    for (int j = 0; j < 9; j++) {
        int a = (int)g_assign[b * N_ + j * 32 + l];
        #pragma unroll
        for (int k = 0; k < K_; k++) m[j][k] = (a == k) ? 1.0f : 0.0f;
    }

    // per-lane selected inverse count (lane l<6 owns output column l)
    float inv[K_];
    #pragma unroll
    for (int k = 0; k < K_; k++) inv[k] = g_inv[b * K_ + k];
    float invSel = inv[0];
    #pragma unroll
    for (int k = 1; k < K_; k++) invSel = (l == k) ? inv[k] : invSel;

    const float* xb = x + (size_t)b * ((size_t)C_ * N_);

    #pragma unroll 1
    for (int i = 0; i < 64; i++) {
        int c = q * 512 + w + i * 8;
        const float* row = xb + (size_t)c * N_;

        float v[9];
        #pragma unroll
        for (int j = 0; j < 9; j++) v[j] = row[j * 32 + l];

        float s[K_];
        #pragma unroll
        for (int k = 0; k < K_; k++) s[k] = 0.f;
        #pragma unroll
        for (int j = 0; j < 9; j++) {
            #pragma unroll
            for (int k = 0; k < K_; k++) s[k] = fmaf(m[j][k], v[j], s[k]);
        }

        // butterfly-reduce all 6 sums across the warp (result in every lane)
        #pragma unroll
        for (int k = 0; k < K_; k++) {
            #pragma unroll
            for (int o = 16; o; o >>= 1) s[k] += __shfl_xor_sync(0xffffffffu, s[k], o);
        }

        float r = s[0];
        #pragma unroll
        for (int k = 1; k < K_; k++) r = (l == k) ? s[k] : r;
        r *= invSel;
        if (l < K_) out[((size_t)b * C_ + c) * K_ + l] = r;
    }
}

extern "C" void kernel_launch(void* const* d_in, const int* in_sizes, int n_in,
                              void* d_out, int out_size) {
    const float* x  = (const float*)d_in[0];   // [B, C, H, W] = [256, 2048, 24, 12]
    const float* cl = (const float*)d_in[1];   // [K, C] = [6, 2048]
    float* out = (float*)d_out;                // [B, C, K]

    assign_kernel<<<B_, N_>>>(x, cl);
    sum_kernel<<<B_ * 4, 256>>>(x, out);
}

// round 3
// speedup vs baseline: 3.7535x; 3.7535x over previous
#include <cuda_runtime.h>

#define B_ 256
#define C_ 2048
#define N_ 288
#define K_ 6

// scratch (no allocations allowed)
__device__ unsigned char g_assign[B_ * N_];
__device__ float g_inv[B_ * K_];
// partial dots: [512 half-blocks][7 (6 dots + xnorm)][288]
__device__ float g_part[(size_t)B_ * 2 * 7 * N_];

// ---------------------------------------------------------------------------
// Kernel A: partial dot products. grid = 2*B (one CTA per (batch, C-half)),
// 288 threads (thread <-> n). Streams half of x[b] coalesced with 8-wide
// prefetch; clusters half staged in 24KB shared.
// ---------------------------------------------------------------------------
__global__ void __launch_bounds__(N_) assign_part_kernel(const float* __restrict__ x,
                                                         const float* __restrict__ cl) {
    __shared__ float sCl[K_][1024];

    const int bx = blockIdx.x;
    const int b = bx >> 1;
    const int half = bx & 1;
    const int t = threadIdx.x;

    for (int i = t; i < K_ * 1024; i += N_) {
        int k = i >> 10, cc = i & 1023;
        sCl[k][cc] = cl[k * C_ + half * 1024 + cc];
    }
    __syncthreads();

    const float* xh = x + (size_t)b * ((size_t)C_ * N_) + (size_t)half * 1024 * N_ + t;

    float d[K_];
    #pragma unroll
    for (int k = 0; k < K_; k++) d[k] = 0.f;
    float xn = 0.f;

    float v[8], vn[8];
    #pragma unroll
    for (int u = 0; u < 8; u++) v[u] = xh[(size_t)u * N_];

    #pragma unroll 1
    for (int c = 0; c < 1024; c += 8) {
        if (c + 8 < 1024) {
            #pragma unroll
            for (int u = 0; u < 8; u++) vn[u] = xh[(size_t)(c + 8 + u) * N_];
        }
        #pragma unroll
        for (int u = 0; u < 8; u++) xn = fmaf(v[u], v[u], xn);
        #pragma unroll
        for (int k = 0; k < K_; k++) {
            float4 q0 = *(const float4*)&sCl[k][c];
            float4 q1 = *(const float4*)&sCl[k][c + 4];
            float a = d[k];
            a = fmaf(v[0], q0.x, a);
            a = fmaf(v[1], q0.y, a);
            a = fmaf(v[2], q0.z, a);
            a = fmaf(v[3], q0.w, a);
            a = fmaf(v[4], q1.x, a);
            a = fmaf(v[5], q1.y, a);
            a = fmaf(v[6], q1.z, a);
            a = fmaf(v[7], q1.w, a);
            d[k] = a;
        }
        #pragma unroll
        for (int u = 0; u < 8; u++) v[u] = vn[u];
    }

    float* p = g_part + (size_t)bx * 7 * N_ + t;
    #pragma unroll
    for (int k = 0; k < K_; k++) p[k * N_] = d[k];
    p[6 * N_] = xn;
}

// ---------------------------------------------------------------------------
// Kernel C: combine partials, argmin, counts. grid = B, 288 threads.
// ---------------------------------------------------------------------------
__global__ void __launch_bounds__(N_) argmin_kernel(const float* __restrict__ cl) {
    __shared__ float sCn[K_];
    __shared__ int   sCnt[K_];

    const int b = blockIdx.x;
    const int t = threadIdx.x;
    const int w = t >> 5;
    const int l = t & 31;

    if (t < K_) sCnt[t] = 0;

    if (w < K_) {
        float s = 0.f;
        for (int c = l; c < C_; c += 32) {
            float v = __ldg(&cl[w * C_ + c]);
            s = fmaf(v, v, s);
        }
        #pragma unroll
        for (int o = 16; o; o >>= 1) s += __shfl_xor_sync(0xffffffffu, s, o);
        if (l == 0) sCn[w] = s;
    }
    __syncthreads();

    const float* p0 = g_part + (size_t)(2 * b) * 7 * N_ + t;
    const float* p1 = g_part + (size_t)(2 * b + 1) * 7 * N_ + t;

    float xn = p0[6 * N_] + p1[6 * N_];
    int   a  = 0;
    float bd = (xn + sCn[0]) - 2.0f * (p0[0] + p1[0]);
    #pragma unroll
    for (int k = 1; k < K_; k++) {
        float e = (xn + sCn[k]) - 2.0f * (p0[k * N_] + p1[k * N_]);
        if (e < bd) { bd = e; a = k; }
    }
    g_assign[b * N_ + t] = (unsigned char)a;

    atomicAdd(&sCnt[a], 1);
    __syncthreads();
    if (t < K_) {
        int cnt = sCnt[t];
        g_inv[b * K_ + t] = (cnt > 0) ? (1.0f / (float)cnt) : 0.0f;
    }
}

// ---------------------------------------------------------------------------
// Kernel B: scatter-mean. grid = 16*B CTAs of 128 threads (4 warps).
// Warp <-> (b, 32 c-rows). Masks precomputed once per warp; prefetch next
// row's 9 loads before reducing current row; split k across warp halves so
// the reduce needs only 15 SHFL (lanes<16 own k0..2, lanes>=16 own k3..5).
// ---------------------------------------------------------------------------
__global__ void __launch_bounds__(128) sum_kernel(const float* __restrict__ x,
                                                  float* __restrict__ out) {
    const int b = blockIdx.x >> 4;
    const int q = blockIdx.x & 15;
    const int w = threadIdx.x >> 5;
    const int l = threadIdx.x & 31;

    // one-hot float masks for this lane's 9 positions (fixed per batch)
    float m[9][K_];
    #pragma unroll
    for (int j = 0; j < 9; j++) {
        int a = (int)g_assign[b * N_ + j * 32 + l];
        #pragma unroll
        for (int k = 0; k < K_; k++) m[j][k] = (a == k) ? 1.0f : 0.0f;
    }

    const bool hi = (l >= 16);
    const int  lk = l & 15;                 // lanes 0..2 of each half write
    const int  myk = lk + (hi ? 3 : 0);
    const float invSel = (lk < 3) ? g_inv[b * K_ + myk] : 0.0f;

    const float* xb = x + (size_t)b * ((size_t)C_ * N_);
    const int c0 = q * 128 + w * 32;        // 32 rows for this warp

    float v[9], vn[9];
    {
        const float* row = xb + (size_t)c0 * N_;
        #pragma unroll
        for (int j = 0; j < 9; j++) v[j] = row[j * 32 + l];
    }

    #pragma unroll 1
    for (int i = 0; i < 32; i++) {
        const int c = c0 + i;
        if (i + 1 < 32) {
            const float* rn = xb + (size_t)(c + 1) * N_;
            #pragma unroll
            for (int j = 0; j < 9; j++) vn[j] = rn[j * 32 + l];
        }

        float s[K_];
        #pragma unroll
        for (int k = 0; k < K_; k++) s[k] = 0.f;
        #pragma unroll
        for (int j = 0; j < 9; j++) {
            #pragma unroll
            for (int k = 0; k < K_; k++) s[k] = fmaf(m[j][k], v[j], s[k]);
        }

        // distributed reduce: low half reduces k0..2, high half k3..5
        float r0 = hi ? s[3] : s[0];
        float r1 = hi ? s[4] : s[1];
        float r2 = hi ? s[5] : s[2];
        float o0 = hi ? s[0] : s[3];
        float o1 = hi ? s[1] : s[4];
        float o2 = hi ? s[2] : s[5];
        r0 += __shfl_xor_sync(0xffffffffu, o0, 16);
        r1 += __shfl_xor_sync(0xffffffffu, o1, 16);
        r2 += __shfl_xor_sync(0xffffffffu, o2, 16);
        #pragma unroll
        for (int o = 8; o; o >>= 1) {
            r0 += __shfl_xor_sync(0xffffffffu, r0, o);
            r1 += __shfl_xor_sync(0xffffffffu, r1, o);
            r2 += __shfl_xor_sync(0xffffffffu, r2, o);
        }

        float res = r0;
        res = (lk == 1) ? r1 : res;
        res = (lk == 2) ? r2 : res;
        if (lk < 3) out[((size_t)b * C_ + c) * K_ + myk] = res * invSel;

        #pragma unroll
        for (int j = 0; j < 9; j++) v[j] = vn[j];
    }
}

extern "C" void kernel_launch(void* const* d_in, const int* in_sizes, int n_in,
                              void* d_out, int out_size) {
    const float* x  = (const float*)d_in[0];   // [256, 2048, 24, 12]
    const float* cl = (const float*)d_in[1];   // [6, 2048]
    float* out = (float*)d_out;                // [B, C, K]

    assign_part_kernel<<<B_ * 2, N_>>>(x, cl);
    argmin_kernel<<<B_, N_>>>(cl);
    sum_kernel<<<B_ * 16, 128>>>(x, out);
}

// round 6
// speedup vs baseline: 3.7964x; 1.0114x over previous
#include <cuda_runtime.h>

#define B_ 256
#define C_ 2048
#define N_ 288
#define K_ 6

typedef unsigned long long u64;

// scratch (no allocations allowed)
__device__ unsigned char g_assign[B_ * N_];
__device__ float g_inv[B_ * K_];
// partial dots: [512 half-blocks][7 (6 dots + xnorm)][288]
__device__ float g_part[(size_t)B_ * 2 * 7 * N_];

__device__ __forceinline__ u64 pack2(float lo, float hi) {
    u64 p;
    asm("mov.b64 %0, {%1, %2};" : "=l"(p) : "f"(lo), "f"(hi));
    return p;
}
__device__ __forceinline__ void unpack2(u64 p, float& lo, float& hi) {
    asm("mov.b64 {%0, %1}, %2;" : "=f"(lo), "=f"(hi) : "l"(p));
}
__device__ __forceinline__ float unpack_sum(u64 p) {
    float lo, hi;
    unpack2(p, lo, hi);
    return lo + hi;
}
__device__ __forceinline__ void fma2(u64& d, u64 a, u64 b) {
    asm("fma.rn.f32x2 %0, %1, %2, %3;" : "=l"(d) : "l"(a), "l"(b), "l"(d));
}

// ---------------------------------------------------------------------------
// Kernel A: partial dot products. grid = 2*B (CTA per (batch, C-half)),
// 288 threads (thread <-> n). Streams x coalesced with 8-wide prefetch;
// cluster half staged in 24KB shared; dots packed as fma.rn.f32x2 (FFMA2).
// ---------------------------------------------------------------------------
__global__ void __launch_bounds__(N_, 4) assign_part_kernel(const float* __restrict__ x,
                                                            const float* __restrict__ cl) {
    __shared__ float sCl[K_][1024];

    const int bx = blockIdx.x;
    const int b = bx >> 1;
    const int half = bx & 1;
    const int t = threadIdx.x;

    for (int i = t; i < K_ * 1024; i += N_) {
        int k = i >> 10, cc = i & 1023;
        sCl[k][cc] = cl[k * C_ + half * 1024 + cc];
    }
    __syncthreads();

    const float* xh = x + (size_t)b * ((size_t)C_ * N_) + (size_t)half * 1024 * N_ + t;

    u64 d2[K_];
    #pragma unroll
    for (int k = 0; k < K_; k++) d2[k] = 0ull;
    u64 xn2 = 0ull;

    float v[8], vn[8];
    #pragma unroll
    for (int u = 0; u < 8; u++) v[u] = xh[(size_t)u * N_];

    #pragma unroll 1
    for (int c = 0; c < 1024; c += 8) {
        if (c + 8 < 1024) {
            #pragma unroll
            for (int u = 0; u < 8; u++) vn[u] = xh[(size_t)(c + 8 + u) * N_];
        }
        u64 vp[4];
        #pragma unroll
        for (int u = 0; u < 4; u++) vp[u] = pack2(v[2 * u], v[2 * u + 1]);
        #pragma unroll
        for (int u = 0; u < 4; u++) fma2(xn2, vp[u], vp[u]);
        #pragma unroll
        for (int k = 0; k < K_; k++) {
            // clusters as packed f32 pairs (16B-aligned: c % 8 == 0)
            ulonglong2 q0 = *(const ulonglong2*)&sCl[k][c];
            ulonglong2 q1 = *(const ulonglong2*)&sCl[k][c + 4];
            fma2(d2[k], vp[0], q0.x);
            fma2(d2[k], vp[1], q0.y);
            fma2(d2[k], vp[2], q1.x);
            fma2(d2[k], vp[3], q1.y);
        }
        #pragma unroll
        for (int u = 0; u < 8; u++) v[u] = vn[u];
    }

    float* p = g_part + (size_t)bx * 7 * N_ + t;
    #pragma unroll
    for (int k = 0; k < K_; k++) p[k * N_] = unpack_sum(d2[k]);
    p[6 * N_] = unpack_sum(xn2);
}

// ---------------------------------------------------------------------------
// Kernel C: combine partials, argmin, counts. grid = B, 288 threads.
// ---------------------------------------------------------------------------
__global__ void __launch_bounds__(N_) argmin_kernel(const float* __restrict__ cl) {
    __shared__ float sCn[K_];
    __shared__ int   sCnt[K_];

    const int b = blockIdx.x;
    const int t = threadIdx.x;
    const int w = t >> 5;
    const int l = t & 31;

    if (t < K_) sCnt[t] = 0;

    if (w < K_) {
        float s = 0.f;
        for (int c = l; c < C_; c += 32) {
            float v = __ldg(&cl[w * C_ + c]);
            s = fmaf(v, v, s);
        }
        #pragma unroll
        for (int o = 16; o; o >>= 1) s += __shfl_xor_sync(0xffffffffu, s, o);
        if (l == 0) sCn[w] = s;
    }
    __syncthreads();

    const float* p0 = g_part + (size_t)(2 * b) * 7 * N_ + t;
    const float* p1 = g_part + (size_t)(2 * b + 1) * 7 * N_ + t;

    float xn = p0[6 * N_] + p1[6 * N_];
    int   a  = 0;
    float bd = (xn + sCn[0]) - 2.0f * (p0[0] + p1[0]);
    #pragma unroll
    for (int k = 1; k < K_; k++) {
        float e = (xn + sCn[k]) - 2.0f * (p0[k * N_] + p1[k * N_]);
        if (e < bd) { bd = e; a = k; }
    }
    g_assign[b * N_ + t] = (unsigned char)a;

    atomicAdd(&sCnt[a], 1);
    __syncthreads();
    if (t < K_) {
        int cnt = sCnt[t];
        g_inv[b * K_ + t] = (cnt > 0) ? (1.0f / (float)cnt) : 0.0f;
    }
}

// ---------------------------------------------------------------------------
// Kernel B: scatter-mean. grid = 16*B CTAs of 128 threads (4 warps).
// Warp <-> (b, 32 c-rows). One-hot masks packed as f32x2 pairs (27 FFMA2 per
// row instead of 54 FFMA); next-row prefetch; split-shuffle reduce (lanes<16
// own k0..2, lanes>=16 own k3..5 -> 15 SHFL per row).
// ---------------------------------------------------------------------------
__global__ void __launch_bounds__(128, 5) sum_kernel(const float* __restrict__ x,
                                                     float* __restrict__ out) {
    const int b = blockIdx.x >> 4;
    const int q = blockIdx.x & 15;
    const int w = threadIdx.x >> 5;
    const int l = threadIdx.x & 31;

    // packed one-hot masks for this lane's 9 positions (fixed per batch):
    // m2[j][p] = (mask[2p], mask[2p+1]) as f32x2
    u64 m2[9][3];
    #pragma unroll
    for (int j = 0; j < 9; j++) {
        int a = (int)g_assign[b * N_ + j * 32 + l];
        #pragma unroll
        for (int p = 0; p < 3; p++)
            m2[j][p] = pack2((a == 2 * p) ? 1.0f : 0.0f,
                             (a == 2 * p + 1) ? 1.0f : 0.0f);
    }

    const bool hi = (l >= 16);
    const int  lk = l & 15;                 // lanes 0..2 of each half write
    const int  myk = lk + (hi ? 3 : 0);
    const float invSel = (lk < 3) ? g_inv[b * K_ + myk] : 0.0f;

    const float* xb = x + (size_t)b * ((size_t)C_ * N_);
    const int c0 = q * 128 + w * 32;        // 32 rows for this warp

    float v[9], vn[9];
    {
        const float* row = xb + (size_t)c0 * N_;
        #pragma unroll
        for (int j = 0; j < 9; j++) v[j] = row[j * 32 + l];
    }

    #pragma unroll 1
    for (int i = 0; i < 32; i++) {
        const int c = c0 + i;
        if (i + 1 < 32) {
            const float* rn = xb + (size_t)(c + 1) * N_;
            #pragma unroll
            for (int j = 0; j < 9; j++) vn[j] = rn[j * 32 + l];
        }

        u64 s2[3];
        #pragma unroll
        for (int p = 0; p < 3; p++) s2[p] = 0ull;
        #pragma unroll
        for (int j = 0; j < 9; j++) {
            u64 vv = pack2(v[j], v[j]);
            #pragma unroll
            for (int p = 0; p < 3; p++) fma2(s2[p], m2[j][p], vv);
        }

        float s[K_];
        unpack2(s2[0], s[0], s[1]);
        unpack2(s2[1], s[2], s[3]);
        unpack2(s2[2], s[4], s[5]);

        // distributed reduce: low half reduces k0..2, high half k3..5
        float r0 = hi ? s[3] : s[0];
        float r1 = hi ? s[4] : s[1];
        float r2 = hi ? s[5] : s[2];
        float o0 = hi ? s[0] : s[3];
        float o1 = hi ? s[1] : s[4];
        float o2 = hi ? s[2] : s[5];
        r0 += __shfl_xor_sync(0xffffffffu, o0, 16);
        r1 += __shfl_xor_sync(0xffffffffu, o1, 16);
        r2 += __shfl_xor_sync(0xffffffffu, o2, 16);
        #pragma unroll
        for (int o = 8; o; o >>= 1) {
            r0 += __shfl_xor_sync(0xffffffffu, r0, o);
            r1 += __shfl_xor_sync(0xffffffffu, r1, o);
            r2 += __shfl_xor_sync(0xffffffffu, r2, o);
        }

        float res = r0;
        res = (lk == 1) ? r1 : res;
        res = (lk == 2) ? r2 : res;
        if (lk < 3) out[((size_t)b * C_ + c) * K_ + myk] = res * invSel;

        #pragma unroll
        for (int j = 0; j < 9; j++) v[j] = vn[j];
    }
}

extern "C" void kernel_launch(void* const* d_in, const int* in_sizes, int n_in,
                              void* d_out, int out_size) {
    const float* x  = (const float*)d_in[0];   // [256, 2048, 24, 12]
    const float* cl = (const float*)d_in[1];   // [6, 2048]
    float* out = (float*)d_out;                // [B, C, K]

    assign_part_kernel<<<B_ * 2, N_>>>(x, cl);
    argmin_kernel<<<B_, N_>>>(cl);
    sum_kernel<<<B_ * 16, 128>>>(x, out);
}